// round 5
// baseline (speedup 1.0000x reference)
#include <cuda_runtime.h>
#include <cuda_bf16.h>
#include <cstdint>

#define TICKS 10000
#define S_BINS 9
#define OUT_CH 64
#define PLANE (S_BINS * TICKS)      // 90000
#define T4 (TICKS / 4)              // 2500

#define NB    296                   // scatter blocks (2 per SM)
#define BTH   512                   // scatter block threads
#define R_REP 16                    // replicas for global REDG path

// Scratch:
__device__ __align__(16) float g_HOT[NB * TICKS];     // per-block SMEM-path histograms, 11.8 MB
__device__ __align__(16) float g_G[R_REP * PLANE];    // replicated global-atomic histograms, 5.8 MB
__device__ __align__(16) float g_BUF[PLANE];          // final suffix-summed buffer

// ---------------------------------------------------------------------------
// K1: zero g_G and g_BUF (g_HOT is fully overwritten by the flush).
// ---------------------------------------------------------------------------
__global__ void k_zero() {
    const int idx = blockIdx.x * blockDim.x + threadIdx.x;
    const int g4 = (R_REP * PLANE) / 4;   // 360000
    const int b4 = PLANE / 4;             // 22500
    float4 z = make_float4(0.f, 0.f, 0.f, 0.f);
    if (idx < g4) reinterpret_cast<float4*>(g_G)[idx] = z;
    if (idx < b4) reinterpret_cast<float4*>(g_BUF)[idx] = z;
}

// ---------------------------------------------------------------------------
// K2: dual-domain scatter (stride==1 fast path):
//   EVEN warps, hot events (x>=2 && y>=2): atomicAdd into 40KB SMEM histogram
//     -> uses per-SM shared-memory atomic throughput
//   ODD warps hot events + ALL rare events: global atomicAdd (REDG, no return)
//     into g_G[replica][bin][t]  -> uses L2/LTS atomic throughput
//   Both domains run concurrently; each handles ~half the 4M ops.
//   flush: SMEM histogram -> g_HOT[blockIdx][*] with plain float4 stores.
// stride!=1 fallback: 9 validity-checked global atomicAdds into g_BUF.
// ---------------------------------------------------------------------------
__global__ void __launch_bounds__(BTH, 2) k_scatter(
        const float* __restrict__ vals,
        const int*   __restrict__ ticks,
        const int*   __restrict__ xs,
        const int*   __restrict__ ys,
        const int*   __restrict__ stride_p,
        int n) {
    __shared__ __align__(16) float hist[TICKS];

    const int st   = *stride_p;
    const int b    = blockIdx.x;
    const int tid  = threadIdx.x;
    const int warp = tid >> 5;

    const int per_block = (((n + NB - 1) / NB) + 3) & ~3;   // multiple of 4
    const int start = b * per_block;
    const int end   = min(n, start + per_block);
    if (start >= n) return;

    if (st == 1) {
        // zero SMEM histogram
        #pragma unroll
        for (int i = tid; i < T4; i += BTH)
            reinterpret_cast<float4*>(hist)[i] = make_float4(0.f, 0.f, 0.f, 0.f);
        __syncthreads();

        const bool use_smem = (warp & 1) == 0;
        float* __restrict__ Grep = g_G + ((b * (BTH / 32) + warp) & (R_REP - 1)) * PLANE;

        const int vec_end = start + ((end - start) & ~3);
        for (int i = start + tid * 4; i + 3 < vec_end; i += BTH * 4) {
            float4 v4 = *reinterpret_cast<const float4*>(vals  + i);
            int4   t4 = *reinterpret_cast<const int4*>  (ticks + i);
            int4   x4 = *reinterpret_cast<const int4*>  (xs    + i);
            int4   y4 = *reinterpret_cast<const int4*>  (ys    + i);
            float v[4] = {v4.x, v4.y, v4.z, v4.w};
            int   t[4] = {t4.x, t4.y, t4.z, t4.w};
            int   x[4] = {x4.x, x4.y, x4.z, x4.w};
            int   y[4] = {y4.x, y4.y, y4.z, y4.w};
            #pragma unroll
            for (int e = 0; e < 4; e++) {
                int cx = x[e] < 2 ? x[e] : 2;
                int cy = y[e] < 2 ? y[e] : 2;
                int bin = cy * 3 + cx;
                if (use_smem && bin == 8)
                    atomicAdd(&hist[t[e]], v[e]);
                else
                    atomicAdd(&Grep[bin * TICKS + t[e]], v[e]);
            }
        }
        // ragged tail (last block only)
        for (int i = vec_end + tid; i < end; i += BTH) {
            float v = vals[i];
            int t = ticks[i], x = xs[i], y = ys[i];
            int cx = x < 2 ? x : 2;
            int cy = y < 2 ? y : 2;
            int bin = cy * 3 + cx;
            if (use_smem && bin == 8)
                atomicAdd(&hist[t], v);
            else
                atomicAdd(&Grep[bin * TICKS + t], v);
        }

        __syncthreads();
        // flush SMEM histogram to per-block global slot (plain stores)
        float4* dst = reinterpret_cast<float4*>(g_HOT + b * TICKS);
        #pragma unroll
        for (int i = tid; i < T4; i += BTH)
            dst[i] = reinterpret_cast<const float4*>(hist)[i];
    } else {
        // generic stride fallback: direct checked atomics into g_BUF
        for (int i = start + tid; i < end; i += BTH) {
            float v = vals[i];
            int t = ticks[i], x = xs[i], y = ys[i];
            #pragma unroll
            for (int ky = 0; ky < 3; ky++)
                #pragma unroll
                for (int kx = 0; kx < 3; kx++) {
                    int ox = x - kx, oy = y - ky;
                    if (ox >= 0 && oy >= 0 && (ox % st) == 0 && (oy % st) == 0)
                        atomicAdd(&g_BUF[(ky * 3 + kx) * TICKS + t], v);
                }
        }
    }
}

// ---------------------------------------------------------------------------
// K3: reduce 16 replica planes + 296 hot slices, then 3x3 2D suffix sum.
// No-op for stride != 1 (g_BUF already final).
// ---------------------------------------------------------------------------
__global__ void k_suffix(const int* __restrict__ stride_p) {
    if (*stride_p != 1) return;
    int t = blockIdx.x * blockDim.x + threadIdx.x;
    if (t >= TICKS) return;

    float g[9];
    #pragma unroll
    for (int bn = 0; bn < 9; bn++) g[bn] = 0.f;

    #pragma unroll
    for (int r = 0; r < R_REP; r++) {
        const float* G = g_G + r * PLANE;
        #pragma unroll
        for (int bn = 0; bn < 9; bn++) g[bn] += G[bn * TICKS + t];
    }
    float hot = 0.f;
    for (int b = 0; b < NB; b++) hot += g_HOT[b * TICKS + t];
    g[8] += hot;

    // suffix over cx within each cy row
    #pragma unroll
    for (int cy = 0; cy < 3; cy++) {
        g[cy * 3 + 1] += g[cy * 3 + 2];
        g[cy * 3 + 0] += g[cy * 3 + 1];
    }
    // suffix over cy within each kx column
    #pragma unroll
    for (int kx = 0; kx < 3; kx++) {
        g[1 * 3 + kx] += g[2 * 3 + kx];
        g[0 * 3 + kx] += g[1 * 3 + kx];
    }

    #pragma unroll
    for (int bn = 0; bn < 9; bn++) g_BUF[bn * TICKS + t] = g[bn];
}

// ---------------------------------------------------------------------------
// K4: broadcast BUF[9][T] to out[64][9][T] (R3 store-parallel form, 7.3us).
// grid = (ceil(T4/128), 9, 16); each thread reads one float4 of BUF and
// writes it into 4 channels.
// ---------------------------------------------------------------------------
__global__ void k_broadcast(float4* __restrict__ out) {
    int col = blockIdx.x * blockDim.x + threadIdx.x;   // 0..T4-1
    if (col >= T4) return;
    int s      = blockIdx.y;                            // 0..8
    int cgroup = blockIdx.z;                            // 0..15 -> channels 4*z..4*z+3
    float4 v = reinterpret_cast<const float4*>(g_BUF)[s * T4 + col];
    float4* dst = out + (cgroup * 4) * (S_BINS * T4) + s * T4 + col;
    #pragma unroll
    for (int c = 0; c < 4; c++)
        dst[c * (S_BINS * T4)] = v;
}

// ---------------------------------------------------------------------------
extern "C" void kernel_launch(void* const* d_in, const int* in_sizes, int n_in,
                              void* d_out, int out_size) {
    const float* vals    = (const float*)d_in[0];
    const int*   ticks   = (const int*)  d_in[1];
    const int*   xs      = (const int*)  d_in[2];
    const int*   ys      = (const int*)  d_in[3];
    const int*   stridep = (const int*)  d_in[4];
    int n = in_sizes[0];

    // K1: zero replica + final buffers
    {
        int total = (R_REP * PLANE) / 4;
        k_zero<<<(total + 255) / 256, 256>>>();
    }
    // K2: dual-domain scatter
    k_scatter<<<NB, BTH>>>(vals, ticks, xs, ys, stridep, n);

    // K3: reduce + suffix sum
    k_suffix<<<(TICKS + 255) / 256, 256>>>(stridep);

    // K4: broadcast to all 64 channels
    {
        dim3 grid((T4 + 127) / 128, S_BINS, 16);
        k_broadcast<<<grid, 128>>>((float4*)d_out);
    }
}

// round 6
// speedup vs baseline: 1.4814x; 1.4814x over previous
#include <cuda_runtime.h>
#include <cuda_bf16.h>
#include <cstdint>

#define TICKS 10000
#define S_BINS 9
#define OUT_CH 64
#define PLANE (S_BINS * TICKS)      // 90000
#define T4 (TICKS / 4)              // 2500

#define NB    148                   // scatter blocks (1 per SM)
#define BTH   1024                  // scatter block threads
#define R_RARE 8                    // replicas for rare-bin global atomics

// Scratch:
__device__ __align__(16) float g_HOT[NB * TICKS];     // per-block hot histograms, 5.9 MB
__device__ __align__(16) float g_G[R_RARE * PLANE];   // rare-bin replicated histograms, 2.9 MB
__device__ __align__(16) float g_BUF[PLANE];          // stride!=1 fallback accumulator

// ---------------------------------------------------------------------------
// K1: zero g_G and g_BUF (g_HOT fully overwritten by flush).
// ---------------------------------------------------------------------------
__global__ void k_zero() {
    const int idx = blockIdx.x * blockDim.x + threadIdx.x;
    const int g4 = (R_RARE * PLANE) / 4;   // 180000
    const int b4 = PLANE / 4;              // 22500
    float4 z = make_float4(0.f, 0.f, 0.f, 0.f);
    if (idx < g4) reinterpret_cast<float4*>(g_G)[idx] = z;
    if (idx < b4) reinterpret_cast<float4*>(g_BUF)[idx] = z;
}

// ---------------------------------------------------------------------------
// K2: scatter (stride==1 fast path):
//   hot events (x>=2 && y>=2, ~97%): atomicAdd into 40KB SMEM tick histogram
//   rare events (~3%): global atomicAdd into g_G[blockIdx&7][bin][t]
//   flush: SMEM histogram -> g_HOT[blockIdx][*] with plain float4 stores.
// stride!=1 fallback: 9 validity-checked global atomicAdds into g_BUF.
// ---------------------------------------------------------------------------
__global__ void __launch_bounds__(BTH, 1) k_scatter(
        const float* __restrict__ vals,
        const int*   __restrict__ ticks,
        const int*   __restrict__ xs,
        const int*   __restrict__ ys,
        const int*   __restrict__ stride_p,
        int n) {
    __shared__ __align__(16) float hist[TICKS];   // 40 KB

    const int st  = *stride_p;
    const int b   = blockIdx.x;
    const int tid = threadIdx.x;

    const int per_block = (((n + NB - 1) / NB) + 3) & ~3;   // multiple of 4
    const int start = b * per_block;
    const int end   = min(n, start + per_block);
    if (start >= n) return;

    if (st == 1) {
        // zero SMEM histogram
        for (int i = tid; i < T4; i += BTH)
            reinterpret_cast<float4*>(hist)[i] = make_float4(0.f, 0.f, 0.f, 0.f);
        __syncthreads();

        float* __restrict__ Grare = g_G + (b & (R_RARE - 1)) * PLANE;

        const int vec_end = start + ((end - start) & ~3);
        for (int i = start + tid * 4; i + 3 < vec_end; i += BTH * 4) {
            float4 v4 = *reinterpret_cast<const float4*>(vals  + i);
            int4   t4 = *reinterpret_cast<const int4*>  (ticks + i);
            int4   x4 = *reinterpret_cast<const int4*>  (xs    + i);
            int4   y4 = *reinterpret_cast<const int4*>  (ys    + i);
            float v[4] = {v4.x, v4.y, v4.z, v4.w};
            int   t[4] = {t4.x, t4.y, t4.z, t4.w};
            int   x[4] = {x4.x, x4.y, x4.z, x4.w};
            int   y[4] = {y4.x, y4.y, y4.z, y4.w};
            #pragma unroll
            for (int e = 0; e < 4; e++) {
                if (x[e] >= 2 && y[e] >= 2) {
                    atomicAdd(&hist[t[e]], v[e]);
                } else {
                    int cx = x[e] < 2 ? x[e] : 2;
                    int cy = y[e] < 2 ? y[e] : 2;
                    atomicAdd(&Grare[(cy * 3 + cx) * TICKS + t[e]], v[e]);
                }
            }
        }
        // ragged tail
        for (int i = vec_end + tid; i < end; i += BTH) {
            float v = vals[i];
            int t = ticks[i], x = xs[i], y = ys[i];
            if (x >= 2 && y >= 2) {
                atomicAdd(&hist[t], v);
            } else {
                int cx = x < 2 ? x : 2;
                int cy = y < 2 ? y : 2;
                atomicAdd(&Grare[(cy * 3 + cx) * TICKS + t], v);
            }
        }

        __syncthreads();
        // flush histogram to per-block slot with plain stores
        float4* dst = reinterpret_cast<float4*>(g_HOT + b * TICKS);
        for (int i = tid; i < T4; i += BTH)
            dst[i] = reinterpret_cast<const float4*>(hist)[i];
    } else {
        for (int i = start + tid; i < end; i += BTH) {
            float v = vals[i];
            int t = ticks[i], x = xs[i], y = ys[i];
            #pragma unroll
            for (int ky = 0; ky < 3; ky++)
                #pragma unroll
                for (int kx = 0; kx < 3; kx++) {
                    int ox = x - kx, oy = y - ky;
                    if (ox >= 0 && oy >= 0 && (ox % st) == 0 && (oy % st) == 0)
                        atomicAdd(&g_BUF[(ky * 3 + kx) * TICKS + t], v);
                }
        }
    }
}

// ---------------------------------------------------------------------------
// K3 (fused finish): per 128-tick tile:
//   reduce 148 hot slices + 8 rare replica planes, 3x3 suffix sum in regs,
//   stage [9][128] in SMEM, then write out[64][9][tile] with coalesced float4.
// stride!=1: read bins straight from g_BUF (already final), broadcast only.
// grid = ceil(TICKS/128) = 79, block = 128.
// ---------------------------------------------------------------------------
__global__ void k_finish(const int* __restrict__ stride_p,
                         float* __restrict__ out) {
    __shared__ __align__(16) float sbuf[S_BINS][128];

    const int t0  = blockIdx.x * 128;
    const int tid = threadIdx.x;
    const int t   = t0 + tid;
    const bool act = (t < TICKS);
    const int st = *stride_p;

    float g[9];
    #pragma unroll
    for (int bn = 0; bn < 9; bn++) g[bn] = 0.f;

    if (act) {
        if (st == 1) {
            // rare replicas
            #pragma unroll
            for (int r = 0; r < R_RARE; r++) {
                const float* G = g_G + r * PLANE;
                #pragma unroll
                for (int bn = 0; bn < 9; bn++) g[bn] += G[bn * TICKS + t];
            }
            // hot slices, unroll 4 for MLP
            float h0 = 0.f, h1 = 0.f, h2 = 0.f, h3 = 0.f;
            #pragma unroll 4
            for (int b = 0; b < NB; b += 4) {
                h0 += g_HOT[(b + 0) * TICKS + t];
                h1 += g_HOT[(b + 1) * TICKS + t];
                h2 += g_HOT[(b + 2) * TICKS + t];
                h3 += g_HOT[(b + 3) * TICKS + t];
            }
            g[8] += (h0 + h1) + (h2 + h3);

            // suffix over cx within each cy row
            #pragma unroll
            for (int cy = 0; cy < 3; cy++) {
                g[cy * 3 + 1] += g[cy * 3 + 2];
                g[cy * 3 + 0] += g[cy * 3 + 1];
            }
            // suffix over cy within each kx column
            #pragma unroll
            for (int kx = 0; kx < 3; kx++) {
                g[1 * 3 + kx] += g[2 * 3 + kx];
                g[0 * 3 + kx] += g[1 * 3 + kx];
            }
        } else {
            #pragma unroll
            for (int bn = 0; bn < 9; bn++) g[bn] = g_BUF[bn * TICKS + t];
        }
    }

    #pragma unroll
    for (int bn = 0; bn < 9; bn++) sbuf[bn][tid] = g[bn];
    __syncthreads();

    // coalesced write-out: nt ticks in this tile (multiple of 4: 128 or 16)
    const int nt  = min(128, TICKS - t0);
    const int nt4 = nt >> 2;
    const int total4 = OUT_CH * S_BINS * 32;   // 18432
    for (int idx = tid; idx < total4; idx += 128) {
        int c    = idx / (S_BINS * 32);
        int rem  = idx - c * (S_BINS * 32);
        int s    = rem >> 5;
        int col4 = rem & 31;
        if (col4 < nt4) {
            float4 v = *reinterpret_cast<const float4*>(&sbuf[s][col4 * 4]);
            *reinterpret_cast<float4*>(out + c * PLANE + s * TICKS + t0 + col4 * 4) = v;
        }
    }
}

// ---------------------------------------------------------------------------
extern "C" void kernel_launch(void* const* d_in, const int* in_sizes, int n_in,
                              void* d_out, int out_size) {
    const float* vals    = (const float*)d_in[0];
    const int*   ticks   = (const int*)  d_in[1];
    const int*   xs      = (const int*)  d_in[2];
    const int*   ys      = (const int*)  d_in[3];
    const int*   stridep = (const int*)  d_in[4];
    int n = in_sizes[0];

    // K1: zero rare + fallback buffers
    {
        int total = (R_RARE * PLANE) / 4;
        k_zero<<<(total + 255) / 256, 256>>>();
    }
    // K2: scatter
    k_scatter<<<NB, BTH>>>(vals, ticks, xs, ys, stridep, n);

    // K3: fused reduce + suffix + broadcast
    k_finish<<<(TICKS + 127) / 128, 128>>>(stridep, (float*)d_out);
}